// round 13
// baseline (speedup 1.0000x reference)
#include <cuda_runtime.h>
#include <cuda_bf16.h>
#include <math.h>

#define NVARS 8
#define NBINS 128
#define GRID  148
#define TPB   256
#define NWARP (TPB / 32)

// Per-block partial min/max, finals, and sync state. Written every run; sync
// counters reset at the end of each run so graph replays start clean.
__device__ float    g_pmin[GRID * NVARS];
__device__ float    g_pmax[GRID * NVARS];
__device__ float    g_fmin[NVARS];
__device__ float    g_fmax[NVARS];
__device__ unsigned g_cnt0 = 0;   // phase-1 arrival
__device__ unsigned g_cnt1 = 0;   // post-spin arrival (for reset)
__device__ unsigned g_flag = 0;   // finals-ready flag

// t_b = b / 127 via PTX div.full.f32 — matches the reference's Triton-emitted
// division in the argmax fusion. DO NOT change to __fdiv_rn.
__device__ __forceinline__ float t_divfull(int b) {
    float t;
    float fb = (float)b;
    asm("div.full.f32 %0, %1, %2;" : "=f"(t) : "f"(fb), "f"(127.0f));
    return t;
}

// Criterion: L1 tree (separate rn mul/add/sub/mul), t via div.full.
__device__ __forceinline__ bool diff_nonpos(float fminv, float d, float feat, int b) {
    float t   = t_divfull(b);
    float dt  = __fmul_rn(d, t);
    float lin = __fadd_rn(fminv, dt);
    float y   = __fmul_rn(__fsub_rn(lin, feat), 1000000.0f);
    return rintf(y) <= 0.0f;
}

// vals/step rollout: lin = fmin + d * rn(b/127), plain mul+add.
__device__ __forceinline__ float lin_at(float fminv, float d, int b) {
    float t = __fdiv_rn((float)b, 127.0f);
    return __fadd_rn(fminv, __fmul_rn(d, t));
}

__device__ __forceinline__ void quant_one(float feat, float fminv, float d,
                                          float step, float& bin_out, float& reg_out) {
    float g = (d > 0.0f) ? ((feat - fminv) / d) * 127.0f : 0.0f;
    int b = (int)g;
    b = max(0, min(NBINS - 1, b));

    while (b < NBINS - 1 && diff_nonpos(fminv, d, feat, b + 1)) b++;
    while (b > 0 && !diff_nonpos(fminv, d, feat, b)) b--;

    float val = lin_at(fminv, d, b);
    bin_out = (float)b;
    reg_out = __fdiv_rn(fmaxf(__fsub_rn(feat, val), 0.0f), step);
}

__global__ void __launch_bounds__(TPB, 1)
fused_quantizer_kernel(const float* __restrict__ feats,
                       float* __restrict__ out_bins,
                       float* __restrict__ out_regs,
                       int nrows) {
    __shared__ float s_mn[NWARP][NVARS];
    __shared__ float s_mx[NWARP][NVARS];
    __shared__ float s_fmin[NVARS], s_d[NVARS], s_step[NVARS];

    const int tid  = threadIdx.x;
    const int bid  = blockIdx.x;
    const int lane = tid & 31;
    const int wid  = tid >> 5;
    const int gthreads = gridDim.x * TPB;

    // ---- Phase 1: per-block min/max partials ----
    float mn[NVARS], mx[NVARS];
#pragma unroll
    for (int c = 0; c < NVARS; c++) { mn[c] = INFINITY; mx[c] = -INFINITY; }

    for (int r = bid * TPB + tid; r < nrows; r += gthreads) {
        const float4* p = reinterpret_cast<const float4*>(feats + (size_t)r * NVARS);
        float4 a = p[0];
        float4 b = p[1];
        mn[0] = fminf(mn[0], a.x); mx[0] = fmaxf(mx[0], a.x);
        mn[1] = fminf(mn[1], a.y); mx[1] = fmaxf(mx[1], a.y);
        mn[2] = fminf(mn[2], a.z); mx[2] = fmaxf(mx[2], a.z);
        mn[3] = fminf(mn[3], a.w); mx[3] = fmaxf(mx[3], a.w);
        mn[4] = fminf(mn[4], b.x); mx[4] = fmaxf(mx[4], b.x);
        mn[5] = fminf(mn[5], b.y); mx[5] = fmaxf(mx[5], b.y);
        mn[6] = fminf(mn[6], b.z); mx[6] = fmaxf(mx[6], b.z);
        mn[7] = fminf(mn[7], b.w); mx[7] = fmaxf(mx[7], b.w);
    }

#pragma unroll
    for (int off = 16; off > 0; off >>= 1) {
#pragma unroll
        for (int c = 0; c < NVARS; c++) {
            mn[c] = fminf(mn[c], __shfl_xor_sync(0xFFFFFFFFu, mn[c], off));
            mx[c] = fmaxf(mx[c], __shfl_xor_sync(0xFFFFFFFFu, mx[c], off));
        }
    }
    if (lane == 0) {
#pragma unroll
        for (int c = 0; c < NVARS; c++) { s_mn[wid][c] = mn[c]; s_mx[wid][c] = mx[c]; }
    }
    __syncthreads();

    if (tid < NVARS) {
        float m = INFINITY, M = -INFINITY;
#pragma unroll
        for (int w = 0; w < NWARP; w++) {
            m = fminf(m, s_mn[w][tid]);
            M = fmaxf(M, s_mx[w][tid]);
        }
        g_pmin[bid * NVARS + tid] = m;
        g_pmax[bid * NVARS + tid] = M;
    }
    __syncthreads();
    __threadfence();

    // ---- Grid sync: last block reduces partials, raises flag ----
    __shared__ unsigned s_ticket;
    if (tid == 0) s_ticket = atomicAdd(&g_cnt0, 1u);
    __syncthreads();

    if (s_ticket == gridDim.x - 1) {
        if (tid < NVARS) {
            float m = INFINITY, M = -INFINITY;
            for (int bb = 0; bb < (int)gridDim.x; bb++) {
                m = fminf(m, g_pmin[bb * NVARS + tid]);
                M = fmaxf(M, g_pmax[bb * NVARS + tid]);
            }
            g_fmin[tid] = m;
            g_fmax[tid] = M;
        }
        __syncthreads();
        __threadfence();
        if (tid == 0) atomicExch(&g_flag, 1u);
    }

    if (tid == 0) {
        while (atomicAdd(&g_flag, 0u) == 0u) __nanosleep(64);
    }
    __syncthreads();

    // Reset sync state once every block has passed the spin (safe: all blocks
    // have observed flag==1 by the time the last one arrives here).
    if (tid == 0) {
        unsigned t2 = atomicAdd(&g_cnt1, 1u);
        if (t2 == gridDim.x - 1) { g_cnt0 = 0u; g_cnt1 = 0u; g_flag = 0u; }
    }

    // ---- Load finals, precompute per-column params ----
    if (tid < NVARS) {
        float fm = g_fmin[tid];
        float fM = g_fmax[tid];
        float d  = __fsub_rn(fM, fm);
        s_fmin[tid] = fm;
        s_d[tid]    = d;
        s_step[tid] = __fsub_rn(lin_at(fm, d, 1), fm);  // lin[0] == fmin exactly
    }
    __syncthreads();

    // ---- Phase 2: quantize (feats re-read is L2-hot) ----
    for (int r = bid * TPB + tid; r < nrows; r += gthreads) {
        const float4* p = reinterpret_cast<const float4*>(feats + (size_t)r * NVARS);
        float4 a = p[0];
        float4 b = p[1];
        float f[NVARS] = {a.x, a.y, a.z, a.w, b.x, b.y, b.z, b.w};

        float bins[NVARS], regs[NVARS];
#pragma unroll
        for (int c = 0; c < NVARS; c++)
            quant_one(f[c], s_fmin[c], s_d[c], s_step[c], bins[c], regs[c]);

        float4* ob = reinterpret_cast<float4*>(out_bins + (size_t)r * NVARS);
        float4* orr = reinterpret_cast<float4*>(out_regs + (size_t)r * NVARS);
        ob[0]  = make_float4(bins[0], bins[1], bins[2], bins[3]);
        ob[1]  = make_float4(bins[4], bins[5], bins[6], bins[7]);
        orr[0] = make_float4(regs[0], regs[1], regs[2], regs[3]);
        orr[1] = make_float4(regs[4], regs[5], regs[6], regs[7]);
    }
}

extern "C" void kernel_launch(void* const* d_in, const int* in_sizes, int n_in,
                              void* d_out, int out_size) {
    const float* feats = (const float*)d_in[0];
    int n = in_sizes[0];
    int nrows = n / NVARS;

    float* out = (float*)d_out;
    float* out_bins = out;       // first n elements: bins (as float32)
    float* out_regs = out + n;   // next n elements: regs

    fused_quantizer_kernel<<<GRID, TPB>>>(feats, out_bins, out_regs, nrows);
}

// round 14
// speedup vs baseline: 2.0172x; 2.0172x over previous
#include <cuda_runtime.h>
#include <cuda_bf16.h>
#include <math.h>

#define NVARS 8
#define NBINS 128
#define GRID  148
#define TPB   1024
#define NWARP (TPB / 32)

// Global min/max in order-preserving uint encoding (sentinels restored by the
// last block each run, so graph replays start clean).
__device__ unsigned g_min_u[NVARS] = {0xFFFFFFFFu,0xFFFFFFFFu,0xFFFFFFFFu,0xFFFFFFFFu,
                                      0xFFFFFFFFu,0xFFFFFFFFu,0xFFFFFFFFu,0xFFFFFFFFu};
__device__ unsigned g_max_u[NVARS] = {0,0,0,0,0,0,0,0};
__device__ unsigned g_cnt0 = 0;   // phase-1 arrivals
__device__ unsigned g_cnt1 = 0;   // end-of-kernel arrivals (reset owner)

__device__ __forceinline__ unsigned f2o(float f) {
    unsigned u = __float_as_uint(f);
    return u ^ ((unsigned)((int)u >> 31) | 0x80000000u);
}
__device__ __forceinline__ float o2f(unsigned u) {
    unsigned b = (u & 0x80000000u) ? (u ^ 0x80000000u) : ~u;
    return __uint_as_float(b);
}

// t_b = b/127 via PTX div.full.f32 — matches the reference's Triton-emitted
// division in the argmax fusion. DO NOT replace with __fdiv_rn.
__device__ __forceinline__ float t_divfull(int b) {
    float t;
    float fb = (float)b;
    asm("div.full.f32 %0, %1, %2;" : "=f"(t) : "f"(fb), "f"(127.0f));
    return t;
}

__global__ void __launch_bounds__(TPB, 1)
fused_quantizer_kernel(const float* __restrict__ feats,
                       float* __restrict__ out_bins,
                       float* __restrict__ out_regs,
                       int nrows) {
    __shared__ float s_mn[NWARP][NVARS];
    __shared__ float s_mx[NWARP][NVARS];
    __shared__ float s_fmin[NVARS], s_d[NVARS], s_step[NVARS], s_inv[NVARS];
    __shared__ float s_linC[NVARS][NBINS];  // criterion lin: fmin + d * t_divfull(b)
    __shared__ float s_linV[NVARS][NBINS];  // vals lin:      fmin + d * rn(b/127)

    const int tid  = threadIdx.x;
    const int bid  = blockIdx.x;
    const int lane = tid & 31;
    const int wid  = tid >> 5;
    const int gthreads = GRID * TPB;

    // ---- Phase 1: min/max ----
    float mn[NVARS], mx[NVARS];
#pragma unroll
    for (int c = 0; c < NVARS; c++) { mn[c] = INFINITY; mx[c] = -INFINITY; }

    for (int r = bid * TPB + tid; r < nrows; r += gthreads) {
        const float4* p = reinterpret_cast<const float4*>(feats + (size_t)r * NVARS);
        float4 a = p[0];
        float4 b = p[1];
        mn[0] = fminf(mn[0], a.x); mx[0] = fmaxf(mx[0], a.x);
        mn[1] = fminf(mn[1], a.y); mx[1] = fmaxf(mx[1], a.y);
        mn[2] = fminf(mn[2], a.z); mx[2] = fmaxf(mx[2], a.z);
        mn[3] = fminf(mn[3], a.w); mx[3] = fmaxf(mx[3], a.w);
        mn[4] = fminf(mn[4], b.x); mx[4] = fmaxf(mx[4], b.x);
        mn[5] = fminf(mn[5], b.y); mx[5] = fmaxf(mx[5], b.y);
        mn[6] = fminf(mn[6], b.z); mx[6] = fmaxf(mx[6], b.z);
        mn[7] = fminf(mn[7], b.w); mx[7] = fmaxf(mx[7], b.w);
    }

#pragma unroll
    for (int off = 16; off > 0; off >>= 1) {
#pragma unroll
        for (int c = 0; c < NVARS; c++) {
            mn[c] = fminf(mn[c], __shfl_xor_sync(0xFFFFFFFFu, mn[c], off));
            mx[c] = fmaxf(mx[c], __shfl_xor_sync(0xFFFFFFFFu, mx[c], off));
        }
    }
    if (lane == 0) {
#pragma unroll
        for (int c = 0; c < NVARS; c++) { s_mn[wid][c] = mn[c]; s_mx[wid][c] = mx[c]; }
    }
    __syncthreads();

    // Warp 0 reduces the 32 warp-slots: lane l -> col l&7, group l>>3 (4 groups of 8 warps)
    if (wid == 0) {
        int c = lane & 7, g = lane >> 3;
        float m = INFINITY, M = -INFINITY;
#pragma unroll
        for (int w = 0; w < 8; w++) {
            m = fminf(m, s_mn[g * 8 + w][c]);
            M = fmaxf(M, s_mx[g * 8 + w][c]);
        }
#pragma unroll
        for (int off = 8; off <= 16; off <<= 1) {
            m = fminf(m, __shfl_xor_sync(0xFFFFFFFFu, m, off));
            M = fmaxf(M, __shfl_xor_sync(0xFFFFFFFFu, M, off));
        }
        if (lane < NVARS) {
            atomicMin(&g_min_u[lane], f2o(m));
            atomicMax(&g_max_u[lane], f2o(M));
        }
        __threadfence();
        if (lane == 0) atomicAdd(&g_cnt0, 1u);
    }

    // ---- Grid sync: poll arrival counter (all blocks resident by design) ----
    if (tid == 0) {
        while (atomicAdd(&g_cnt0, 0u) < (unsigned)GRID) { }
    }
    __syncthreads();
    __threadfence();

    // ---- Build per-column params + per-(col,bin) LUTs (1024 = 8*128 threads) ----
    if (tid < NVARS) {
        float fm = o2f(g_min_u[tid]);
        float fM = o2f(g_max_u[tid]);
        float d  = __fsub_rn(fM, fm);
        s_fmin[tid] = fm;
        s_d[tid]    = d;
        // step = lin[1]-lin[0] with rn-t mul+add; lin[0]==fmin exactly
        float t1 = __fdiv_rn(1.0f, 127.0f);
        s_step[tid] = __fsub_rn(__fadd_rn(fm, __fmul_rn(d, t1)), fm);
        s_inv[tid]  = (d > 0.0f) ? (127.0f / d) : 0.0f;  // guess only, any rounding
    }
    __syncthreads();
    {
        int c = tid >> 7;          // 0..7
        int b = tid & (NBINS - 1); // 0..127
        float fm = s_fmin[c], d = s_d[c];
        s_linC[c][b] = __fadd_rn(fm, __fmul_rn(d, t_divfull(b)));
        s_linV[c][b] = __fadd_rn(fm, __fmul_rn(d, __fdiv_rn((float)b, 127.0f)));
    }
    __syncthreads();

    // ---- Phase 2: quantize (feats re-read is L2-hot) ----
    for (int r = bid * TPB + tid; r < nrows; r += gthreads) {
        const float4* p = reinterpret_cast<const float4*>(feats + (size_t)r * NVARS);
        float4 a = p[0];
        float4 b4 = p[1];
        float f[NVARS] = {a.x, a.y, a.z, a.w, b4.x, b4.y, b4.z, b4.w};

        float bins[NVARS], regs[NVARS];
#pragma unroll
        for (int c = 0; c < NVARS; c++) {
            float feat = f[c];
            // guess
            int b = (int)((feat - s_fmin[c]) * s_inv[c]);
            b = max(0, min(NBINS - 1, b));
            // fixup under criterion: rint((linC[b] - feat)*1e6) <= 0
            while (b < NBINS - 1 &&
                   rintf(__fmul_rn(__fsub_rn(s_linC[c][b + 1], feat), 1000000.0f)) <= 0.0f) b++;
            while (b > 0 &&
                   !(rintf(__fmul_rn(__fsub_rn(s_linC[c][b], feat), 1000000.0f)) <= 0.0f)) b--;

            float val = s_linV[c][b];
            bins[c] = (float)b;
            regs[c] = __fdiv_rn(fmaxf(__fsub_rn(feat, val), 0.0f), s_step[c]);
        }

        float4* ob  = reinterpret_cast<float4*>(out_bins + (size_t)r * NVARS);
        float4* orr = reinterpret_cast<float4*>(out_regs + (size_t)r * NVARS);
        ob[0]  = make_float4(bins[0], bins[1], bins[2], bins[3]);
        ob[1]  = make_float4(bins[4], bins[5], bins[6], bins[7]);
        orr[0] = make_float4(regs[0], regs[1], regs[2], regs[3]);
        orr[1] = make_float4(regs[4], regs[5], regs[6], regs[7]);
    }

    // ---- Reset sync state + sentinels for the next graph replay ----
    __syncthreads();
    if (tid == 0) {
        unsigned t2 = atomicAdd(&g_cnt1, 1u);
        if (t2 == (unsigned)GRID - 1u) {
#pragma unroll
            for (int c = 0; c < NVARS; c++) {
                g_min_u[c] = 0xFFFFFFFFu;
                g_max_u[c] = 0u;
            }
            g_cnt0 = 0u;
            __threadfence();
            g_cnt1 = 0u;
        }
    }
}

extern "C" void kernel_launch(void* const* d_in, const int* in_sizes, int n_in,
                              void* d_out, int out_size) {
    const float* feats = (const float*)d_in[0];
    int n = in_sizes[0];
    int nrows = n / NVARS;

    float* out = (float*)d_out;
    float* out_bins = out;       // first n elements: bins (as float32)
    float* out_regs = out + n;   // next n elements: regs

    fused_quantizer_kernel<<<GRID, TPB>>>(feats, out_bins, out_regs, nrows);
}